// round 8
// baseline (speedup 1.0000x reference)
#include <cuda_runtime.h>

// ---------------------------------------------------------------------------
// Binarized 5-layer MLP, B=32768:
//   L0: 784->256, L1-3: 256->256, L4: 256->10, each: binarize(a) @ binarize(W).T
//   then training-mode BatchNorm over batch; final softmax.
//
// Each GEMM block: (1) computes the previous layer's BN affine from exact
// integer stats (double math, redundant per block), (2) binarizes its own 64
// rows ONCE into a shared-memory bit tile, (3) runs a pure XNOR/popc GEMM
// with activation quads via uniform LDS.128 broadcast (no shfl) and weights
// via conflict-free padded-stride LDS.128, (4) writes pre-BN h (in-place)
// and accumulates exact column stats (S1,S2) via i64 atomics.
// ---------------------------------------------------------------------------

#define BATCH 32768
#define L0_IN 784
#define L0_WORDS 25    // ceil(784/32)
#define L0_WPAD 28     // 28*{0..7} mod 32 hits distinct 4-groups -> LDS.128 conflict-free
#define MID_WORDS 8    // 256/32
#define MID_WPAD 12    // 12*{0..7} mod 32 distinct 4-groups -> LDS.128 conflict-free
#define EPSV 1e-5

// Scratch (no allocations allowed -> __device__ globals)
__device__ unsigned int g_Xb[BATCH * L0_WORDS];      // packed input bits
__device__ unsigned int g_Wb0[256 * L0_WORDS];       // packed W0
__device__ unsigned int g_WbM[3][256 * MID_WORDS];   // packed W1..W3
__device__ unsigned int g_Wb4[10 * MID_WORDS];       // packed W4
__device__ short        g_H[BATCH * 256];            // pre-BN activations (in-place reuse)
__device__ short        g_H4[BATCH * 10];            // last layer pre-BN
__device__ long long    g_S1[5][256];                // per-column sum(h)
__device__ long long    g_S2[5][256];                // per-column sum(h^2)

// ---------------------------------------------------------------------------
__global__ void zero_stats_kernel() {
    int i = blockIdx.x * blockDim.x + threadIdx.x;
    if (i < 5 * 256) {
        g_S1[i >> 8][i & 255] = 0;
        g_S2[i >> 8][i & 255] = 0;
    }
}

// ---------------------------------------------------------------------------
// One warp packs one row: bit j of word w = ((src[row][32w+j] - sub) >= 0).
__device__ __forceinline__ void pack_rows(const float* __restrict__ src,
                                          unsigned int* __restrict__ dst,
                                          int row, int rows, int in_dim,
                                          int words, float sub) {
    if (row >= rows) return;
    int lane = threadIdx.x & 31;
    long base = (long)row * in_dim;
    for (int w = 0; w < words; w++) {
        int c = (w << 5) + lane;
        bool p = (c < in_dim) && ((src[base + c] - sub) >= 0.0f);
        unsigned int m = __ballot_sync(0xffffffffu, p);
        if (lane == 0) dst[row * words + w] = m;
    }
}

// Single prep kernel: packs x + all weight matrices.
__global__ __launch_bounds__(256) void prep_kernel(
    const float* __restrict__ x,  const float* __restrict__ W0,
    const float* __restrict__ W1, const float* __restrict__ W2,
    const float* __restrict__ W3, const float* __restrict__ W4) {
    int b = blockIdx.x;
    int warp = threadIdx.x >> 5;
    if (b < 4096) {
        pack_rows(x, g_Xb, b * 8 + warp, BATCH, L0_IN, L0_WORDS, 0.5f);
    } else if (b < 4128) {
        pack_rows(W0, g_Wb0, (b - 4096) * 8 + warp, 256, L0_IN, L0_WORDS, 0.0f);
    } else if (b < 4160) {
        pack_rows(W1, g_WbM[0], (b - 4128) * 8 + warp, 256, 256, MID_WORDS, 0.0f);
    } else if (b < 4192) {
        pack_rows(W2, g_WbM[1], (b - 4160) * 8 + warp, 256, 256, MID_WORDS, 0.0f);
    } else if (b < 4224) {
        pack_rows(W3, g_WbM[2], (b - 4192) * 8 + warp, 256, 256, MID_WORDS, 0.0f);
    } else {
        pack_rows(W4, g_Wb4, (b - 4224) * 8 + warp, 10, 256, MID_WORDS, 0.0f);
    }
}

// ---------------------------------------------------------------------------
// Per-column BN affine y = A*h + beta for `layer` from exact integer stats
// (redundant per block; 256 threads, one column each; exact double math).
__device__ __forceinline__ void compute_norm(float2* sN, int layer,
                                             const float* __restrict__ g,
                                             const float* __restrict__ b) {
    int c = threadIdx.x;
    double m = (double)g_S1[layer][c] / (double)BATCH;
    double v = (double)g_S2[layer][c] / (double)BATCH - m * m;
    double r = 1.0 / sqrt(v + EPSV);
    double A = (double)g[c] * r;
    double beta = (double)b[c] - A * m;
    sN[c] = make_float2((float)A, (float)beta);
}

// ---------------------------------------------------------------------------
// Binarize nrows rows of g_H (this warp's rows) into the block's smem bit
// tile. sAct stride = MID_WORDS words per row.
__device__ __forceinline__ void binarize_rows(unsigned int* sAct,
                                              const float2* sN,
                                              int rbase, int warp, int lane,
                                              int nrows) {
    for (int r = 0; r < nrows; r++) {
        int lrow = warp * nrows + r;
        const short* hp = &g_H[(rbase + lrow) * 256];
#pragma unroll
        for (int w = 0; w < 8; w++) {
            int c = (w << 5) + lane;
            float2 nb = sN[c];
            float h = (float)hp[c];
            unsigned int m = __ballot_sync(0xffffffffu, fmaf(nb.x, h, nb.y) >= 0.0f);
            if (lane == w) sAct[lrow * MID_WORDS + w] = m;
        }
    }
}

// ---------------------------------------------------------------------------
// Layer 0: h = 784 - 2*popc(xor). K padded 25->28 words with zeros on BOTH
// operands (0^0 contributes 0 to popc). Block = 8 warps x 8 rows = 64 rows;
// warp does 2 passes x 4 rows; lane owns 8 columns.
__global__ __launch_bounds__(256, 3) void gemm0_kernel() {
    __shared__ __align__(16) unsigned int sW[256 * L0_WPAD];   // 28.7 KB
    __shared__ __align__(16) unsigned int sAct[64 * L0_WPAD];  // 7.2 KB
    __shared__ int sS1[256], sS2[256];
    int tid = threadIdx.x;
    int rbase = blockIdx.x * 64;
    for (int idx = tid; idx < 256 * L0_WPAD; idx += 256) {
        int col = idx / L0_WPAD, w = idx - col * L0_WPAD;
        sW[idx] = (w < L0_WORDS) ? g_Wb0[col * L0_WORDS + w] : 0u;
    }
    for (int idx = tid; idx < 64 * L0_WPAD; idx += 256) {
        int r = idx / L0_WPAD, w = idx - r * L0_WPAD;
        sAct[idx] = (w < L0_WORDS) ? g_Xb[(rbase + r) * L0_WORDS + w] : 0u;
    }
    sS1[tid] = 0; sS2[tid] = 0;
    __syncthreads();

    int warp = tid >> 5, lane = tid & 31;
    int ls1[8], ls2[8];
#pragma unroll
    for (int c8 = 0; c8 < 8; c8++) { ls1[c8] = 0; ls2[c8] = 0; }

#pragma unroll 1
    for (int it = 0; it < 2; it++) {
        int r0 = warp * 8 + it * 4;     // local row of first of 4
        int acc[4][8];
#pragma unroll
        for (int r = 0; r < 4; r++)
#pragma unroll
            for (int c8 = 0; c8 < 8; c8++) acc[r][c8] = 0;

#pragma unroll 1
        for (int q = 0; q < 7; q++) {   // 7 quads cover padded words 0..27
            uint4 a0 = *(const uint4*)&sAct[(r0 + 0) * L0_WPAD + (q << 2)];
            uint4 a1 = *(const uint4*)&sAct[(r0 + 1) * L0_WPAD + (q << 2)];
            uint4 a2 = *(const uint4*)&sAct[(r0 + 2) * L0_WPAD + (q << 2)];
            uint4 a3 = *(const uint4*)&sAct[(r0 + 3) * L0_WPAD + (q << 2)];
#pragma unroll
            for (int c8 = 0; c8 < 8; c8++) {
                uint4 wv = *(const uint4*)&sW[(lane + (c8 << 5)) * L0_WPAD + (q << 2)];
                acc[0][c8] += __popc(a0.x ^ wv.x) + __popc(a0.y ^ wv.y)
                            + __popc(a0.z ^ wv.z) + __popc(a0.w ^ wv.w);
                acc[1][c8] += __popc(a1.x ^ wv.x) + __popc(a1.y ^ wv.y)
                            + __popc(a1.z ^ wv.z) + __popc(a1.w ^ wv.w);
                acc[2][c8] += __popc(a2.x ^ wv.x) + __popc(a2.y ^ wv.y)
                            + __popc(a2.z ^ wv.z) + __popc(a2.w ^ wv.w);
                acc[3][c8] += __popc(a3.x ^ wv.x) + __popc(a3.y ^ wv.y)
                            + __popc(a3.z ^ wv.z) + __popc(a3.w ^ wv.w);
            }
        }
#pragma unroll
        for (int c8 = 0; c8 < 8; c8++) {
            int col = lane + (c8 << 5);
#pragma unroll
            for (int r = 0; r < 4; r++) {
                int h = L0_IN - 2 * acc[r][c8];
                g_H[(rbase + r0 + r) * 256 + col] = (short)h;
                ls1[c8] += h;
                ls2[c8] += h * h;
            }
        }
    }
#pragma unroll
    for (int c8 = 0; c8 < 8; c8++) {
        int col = lane + (c8 << 5);
        atomicAdd(&sS1[col], ls1[c8]);
        atomicAdd(&sS2[col], ls2[c8]);
    }
    __syncthreads();
    atomicAdd((unsigned long long*)&g_S1[0][tid], (unsigned long long)(long long)sS1[tid]);
    atomicAdd((unsigned long long*)&g_S2[0][tid], (unsigned long long)(long long)sS2[tid]);
}

// ---------------------------------------------------------------------------
// Middle layers 1..3: block binarizes its 64 rows of g_H into sAct (prologue,
// using the previous layer's BN affine computed from exact stats), then pure
// bit GEMM; h written back IN-PLACE (block touches only its own rows).
__global__ __launch_bounds__(256, 3) void gemm_mid_kernel(
    int wIdx, int statIdx,
    const float* __restrict__ gPrev, const float* __restrict__ bPrev) {
    __shared__ __align__(16) unsigned int sW[256 * MID_WPAD];   // 12.3 KB
    __shared__ __align__(16) unsigned int sAct[64 * MID_WORDS]; // 2 KB
    __shared__ float2 sN[256];
    __shared__ int sS1[256], sS2[256];
    const unsigned int* __restrict__ Wb = g_WbM[wIdx];
    int tid = threadIdx.x;
    int rbase = blockIdx.x * 64;
    for (int i = tid; i < 256 * MID_WORDS; i += 256) {
        int col = i >> 3, w = i & 7;
        sW[col * MID_WPAD + w] = Wb[i];
    }
    compute_norm(sN, statIdx - 1, gPrev, bPrev);
    sS1[tid] = 0; sS2[tid] = 0;
    __syncthreads();

    int warp = tid >> 5, lane = tid & 31;
    binarize_rows(sAct, sN, rbase, warp, lane, 8);
    __syncthreads();

    int ls1[8], ls2[8];
#pragma unroll
    for (int c8 = 0; c8 < 8; c8++) { ls1[c8] = 0; ls2[c8] = 0; }

#pragma unroll 1
    for (int it = 0; it < 2; it++) {
        int r0 = warp * 8 + it * 4;
        int acc[4][8];
#pragma unroll
        for (int r = 0; r < 4; r++)
#pragma unroll
            for (int c8 = 0; c8 < 8; c8++) acc[r][c8] = 0;

#pragma unroll
        for (int q = 0; q < 2; q++) {
            uint4 a0 = *(const uint4*)&sAct[(r0 + 0) * MID_WORDS + (q << 2)];
            uint4 a1 = *(const uint4*)&sAct[(r0 + 1) * MID_WORDS + (q << 2)];
            uint4 a2 = *(const uint4*)&sAct[(r0 + 2) * MID_WORDS + (q << 2)];
            uint4 a3 = *(const uint4*)&sAct[(r0 + 3) * MID_WORDS + (q << 2)];
#pragma unroll
            for (int c8 = 0; c8 < 8; c8++) {
                uint4 wv = *(const uint4*)&sW[((c8 << 5) + lane) * MID_WPAD + (q << 2)];
                acc[0][c8] += __popc(a0.x ^ wv.x) + __popc(a0.y ^ wv.y)
                            + __popc(a0.z ^ wv.z) + __popc(a0.w ^ wv.w);
                acc[1][c8] += __popc(a1.x ^ wv.x) + __popc(a1.y ^ wv.y)
                            + __popc(a1.z ^ wv.z) + __popc(a1.w ^ wv.w);
                acc[2][c8] += __popc(a2.x ^ wv.x) + __popc(a2.y ^ wv.y)
                            + __popc(a2.z ^ wv.z) + __popc(a2.w ^ wv.w);
                acc[3][c8] += __popc(a3.x ^ wv.x) + __popc(a3.y ^ wv.y)
                            + __popc(a3.z ^ wv.z) + __popc(a3.w ^ wv.w);
            }
        }
#pragma unroll
        for (int c8 = 0; c8 < 8; c8++) {
            int col = (c8 << 5) + lane;
#pragma unroll
            for (int r = 0; r < 4; r++) {
                int h = 256 - 2 * acc[r][c8];
                g_H[(rbase + r0 + r) * 256 + col] = (short)h;
                ls1[c8] += h;
                ls2[c8] += h * h;
            }
        }
    }
#pragma unroll
    for (int c8 = 0; c8 < 8; c8++) {
        int col = (c8 << 5) + lane;
        atomicAdd(&sS1[col], ls1[c8]);
        atomicAdd(&sS2[col], ls2[c8]);
    }
    __syncthreads();
    atomicAdd((unsigned long long*)&g_S1[statIdx][tid], (unsigned long long)(long long)sS1[tid]);
    atomicAdd((unsigned long long*)&g_S2[statIdx][tid], (unsigned long long)(long long)sS2[tid]);
}

// ---------------------------------------------------------------------------
// Layer 4: 256 -> 10. Block binarizes 128 rows of H3 into smem, lanes 0..9
// own the 10 output columns.
__global__ __launch_bounds__(256) void gemm4_kernel(
    const float* __restrict__ g3, const float* __restrict__ b3) {
    __shared__ unsigned int sW[10 * MID_WORDS];
    __shared__ unsigned int sAct[128 * MID_WORDS];  // 4 KB
    __shared__ float2 sN[256];
    int tid = threadIdx.x;
    if (tid < 10 * MID_WORDS) sW[tid] = g_Wb4[tid];
    compute_norm(sN, 3, g3, b3);
    __syncthreads();

    int warp = tid >> 5, lane = tid & 31;
    int rbase = blockIdx.x * 128;
    binarize_rows(sAct, sN, rbase, warp, lane, 16);
    __syncthreads();

    int ls1 = 0, ls2 = 0;
#pragma unroll 1
    for (int r = 0; r < 16; r++) {
        int lrow = warp * 16 + r;
        if (lane < 10) {
            const unsigned int* ap = &sAct[lrow * MID_WORDS];
            int acc = 0;
#pragma unroll
            for (int w = 0; w < 8; w++)
                acc += __popc(ap[w] ^ sW[lane * MID_WORDS + w]);
            int h = 256 - 2 * acc;
            g_H4[(rbase + lrow) * 10 + lane] = (short)h;
            ls1 += h; ls2 += h * h;
        }
    }
    if (lane < 10) {
        atomicAdd((unsigned long long*)&g_S1[4][lane], (unsigned long long)(long long)ls1);
        atomicAdd((unsigned long long*)&g_S2[4][lane], (unsigned long long)(long long)ls2);
    }
}

// ---------------------------------------------------------------------------
// Final BN (from exact stats) + softmax, thread per row.
__global__ __launch_bounds__(256) void softmax_kernel(
    const float* __restrict__ g4, const float* __restrict__ b4,
    float* __restrict__ out) {
    __shared__ float2 sN[10];
    if (threadIdx.x < 10) {
        int c = threadIdx.x;
        double m = (double)g_S1[4][c] / (double)BATCH;
        double v = (double)g_S2[4][c] / (double)BATCH - m * m;
        double r = 1.0 / sqrt(v + EPSV);
        double A = (double)g4[c] * r;
        sN[c] = make_float2((float)A, (float)((double)b4[c] - A * m));
    }
    __syncthreads();
    int row = blockIdx.x * blockDim.x + threadIdx.x;
    if (row >= BATCH) return;
    float y[10];
    float mx = -1e30f;
#pragma unroll
    for (int i = 0; i < 10; i++) {
        y[i] = fmaf(sN[i].x, (float)g_H4[row * 10 + i], sN[i].y);
        mx = fmaxf(mx, y[i]);
    }
    float s = 0.0f;
#pragma unroll
    for (int i = 0; i < 10; i++) {
        y[i] = expf(y[i] - mx);
        s += y[i];
    }
    float inv = 1.0f / s;
#pragma unroll
    for (int i = 0; i < 10; i++)
        out[row * 10 + i] = y[i] * inv;
}

// ---------------------------------------------------------------------------
extern "C" void kernel_launch(void* const* d_in, const int* in_sizes, int n_in,
                              void* d_out, int out_size) {
    const float* x = (const float*)d_in[0];
    const float *W[5], *G[5], *Bv[5];
    // setup_inputs dict order interleaves (W,g,b); signature order groups them.
    bool interleaved = (n_in >= 16) && (in_sizes[2] == 256) && (in_sizes[3] == 256);
    if (interleaved) {
        int idx = 1;
        for (int k = 0; k < 5; k++) {
            W[k]  = (const float*)d_in[idx + 0];
            G[k]  = (const float*)d_in[idx + 1];
            Bv[k] = (const float*)d_in[idx + 2];
            idx += 3;
        }
    } else {
        for (int k = 0; k < 5; k++) {
            W[k]  = (const float*)d_in[1 + k];
            G[k]  = (const float*)d_in[6 + k];
            Bv[k] = (const float*)d_in[11 + k];
        }
    }

    // Launch order: ncu (-s 5 -c 1) lands on launch #6 = last gemm_mid.
    zero_stats_kernel<<<5, 256>>>();                               // 1
    prep_kernel<<<4226, 256>>>(x, W[0], W[1], W[2], W[3], W[4]);   // 2
    gemm0_kernel<<<BATCH / 64, 256>>>();                           // 3
    gemm_mid_kernel<<<BATCH / 64, 256>>>(0, 1, G[0], Bv[0]);       // 4
    gemm_mid_kernel<<<BATCH / 64, 256>>>(1, 2, G[1], Bv[1]);       // 5
    gemm_mid_kernel<<<BATCH / 64, 256>>>(2, 3, G[2], Bv[2]);       // 6 <- profiled
    gemm4_kernel<<<BATCH / 128, 256>>>(G[3], Bv[3]);               // 7
    softmax_kernel<<<BATCH / 256, 256>>>(G[4], Bv[4], (float*)d_out); // 8
    (void)out_size;
}

// round 12
// speedup vs baseline: 1.0054x; 1.0054x over previous
#include <cuda_runtime.h>

// ---------------------------------------------------------------------------
// Binarized 5-layer MLP, B=32768:
//   L0: 784->256, L1-3: 256->256, L4: 256->10, each: binarize(a) @ binarize(W).T
//   then training-mode BatchNorm over batch; final softmax.
//
// GEMM kernels: block computes prev-layer BN affine from exact integer stats
// (double math), binarizes its own 64 rows once into a per-warp smem bit tile
// (warp-local sync only), then runs XNOR/popc GEMM in 2 column-halves x
// 2 row-halves (acc[4][4], <=64 regs) so 4 CTAs/SM -> the 512-block grid is a
// SINGLE wave. Weights via conflict-free padded-stride LDS.128; activations
// via uniform LDS.128 broadcast. Exact column stats via i64 atomics.
// ---------------------------------------------------------------------------

#define BATCH 32768
#define L0_IN 784
#define L0_WORDS 25    // ceil(784/32)
#define L0_WPAD 28     // 28*{0..7} mod 32 distinct 4-groups -> LDS.128 conflict-free
#define MID_WORDS 8    // 256/32
#define MID_WPAD 12    // 12*{0..7} mod 32 distinct 4-groups -> LDS.128 conflict-free
#define EPSV 1e-5

// Scratch (no allocations allowed -> __device__ globals)
__device__ unsigned int g_Xb[BATCH * L0_WORDS];      // packed input bits
__device__ unsigned int g_Wb0[256 * L0_WORDS];       // packed W0
__device__ unsigned int g_WbM[3][256 * MID_WORDS];   // packed W1..W3
__device__ unsigned int g_Wb4[10 * MID_WORDS];       // packed W4
__device__ short        g_H[BATCH * 256];            // pre-BN activations (in-place reuse)
__device__ short        g_H4[BATCH * 10];            // last layer pre-BN
__device__ long long    g_S1[5][256];                // per-column sum(h)
__device__ long long    g_S2[5][256];                // per-column sum(h^2)

// ---------------------------------------------------------------------------
__global__ void zero_stats_kernel() {
    int i = blockIdx.x * blockDim.x + threadIdx.x;
    if (i < 5 * 256) {
        g_S1[i >> 8][i & 255] = 0;
        g_S2[i >> 8][i & 255] = 0;
    }
}

// ---------------------------------------------------------------------------
// One warp packs one row: bit j of word w = ((src[row][32w+j] - sub) >= 0).
__device__ __forceinline__ void pack_rows(const float* __restrict__ src,
                                          unsigned int* __restrict__ dst,
                                          int row, int rows, int in_dim,
                                          int words, float sub) {
    if (row >= rows) return;
    int lane = threadIdx.x & 31;
    long base = (long)row * in_dim;
    for (int w = 0; w < words; w++) {
        int c = (w << 5) + lane;
        bool p = (c < in_dim) && ((src[base + c] - sub) >= 0.0f);
        unsigned int m = __ballot_sync(0xffffffffu, p);
        if (lane == 0) dst[row * words + w] = m;
    }
}

// Single prep kernel: packs x + all weight matrices.
__global__ __launch_bounds__(256) void prep_kernel(
    const float* __restrict__ x,  const float* __restrict__ W0,
    const float* __restrict__ W1, const float* __restrict__ W2,
    const float* __restrict__ W3, const float* __restrict__ W4) {
    int b = blockIdx.x;
    int warp = threadIdx.x >> 5;
    if (b < 4096) {
        pack_rows(x, g_Xb, b * 8 + warp, BATCH, L0_IN, L0_WORDS, 0.5f);
    } else if (b < 4128) {
        pack_rows(W0, g_Wb0, (b - 4096) * 8 + warp, 256, L0_IN, L0_WORDS, 0.0f);
    } else if (b < 4160) {
        pack_rows(W1, g_WbM[0], (b - 4128) * 8 + warp, 256, 256, MID_WORDS, 0.0f);
    } else if (b < 4192) {
        pack_rows(W2, g_WbM[1], (b - 4160) * 8 + warp, 256, 256, MID_WORDS, 0.0f);
    } else if (b < 4224) {
        pack_rows(W3, g_WbM[2], (b - 4192) * 8 + warp, 256, 256, MID_WORDS, 0.0f);
    } else {
        pack_rows(W4, g_Wb4, (b - 4224) * 8 + warp, 10, 256, MID_WORDS, 0.0f);
    }
}

// ---------------------------------------------------------------------------
// Per-column BN affine y = A*h + beta for `layer` from exact integer stats
// (redundant per block; 256 threads, one column each; exact double math).
__device__ __forceinline__ void compute_norm(float2* sN, int layer,
                                             const float* __restrict__ g,
                                             const float* __restrict__ b) {
    int c = threadIdx.x;
    double m = (double)g_S1[layer][c] / (double)BATCH;
    double v = (double)g_S2[layer][c] / (double)BATCH - m * m;
    double r = 1.0 / sqrt(v + EPSV);
    double A = (double)g[c] * r;
    double beta = (double)b[c] - A * m;
    sN[c] = make_float2((float)A, (float)beta);
}

// ---------------------------------------------------------------------------
// popc of a quad xor
__device__ __forceinline__ int popc4(uint4 a, uint4 w) {
    return __popc(a.x ^ w.x) + __popc(a.y ^ w.y)
         + __popc(a.z ^ w.z) + __popc(a.w ^ w.w);
}

// ---------------------------------------------------------------------------
// Layer 0: h = 784 - 2*popc(xor). K padded 25->28 words with zeros on both
// operands. Block = 8 warps x 8 rows = 64 rows; each thread: 2 col-halves x
// 2 row-halves with acc[4][4]. Single wave at 4 CTAs/SM.
__global__ __launch_bounds__(256, 4) void gemm0_kernel() {
    __shared__ __align__(16) unsigned int sW[256 * L0_WPAD];   // 28.7 KB
    __shared__ __align__(16) unsigned int sAct[64 * L0_WPAD];  // 7.2 KB
    __shared__ int sS1[256], sS2[256];
    int tid = threadIdx.x;
    int rbase = blockIdx.x * 64;
    for (int idx = tid; idx < 256 * L0_WPAD; idx += 256) {
        int col = idx / L0_WPAD, w = idx - col * L0_WPAD;
        sW[idx] = (w < L0_WORDS) ? g_Wb0[col * L0_WORDS + w] : 0u;
    }
    sS1[tid] = 0; sS2[tid] = 0;
    __syncthreads();

    int warp = tid >> 5, lane = tid & 31;
    // Per-warp: fill own 8 rows of the activation tile (warp-local only).
    for (int i = lane; i < 8 * L0_WPAD; i += 32) {
        int r = i / L0_WPAD, w = i - r * L0_WPAD;
        int lrow = warp * 8 + r;
        sAct[lrow * L0_WPAD + w] =
            (w < L0_WORDS) ? g_Xb[(rbase + lrow) * L0_WORDS + w] : 0u;
    }
    __syncwarp();

#pragma unroll
    for (int ch = 0; ch < 2; ch++) {            // column half
        int ls1[4] = {0, 0, 0, 0}, ls2[4] = {0, 0, 0, 0};
#pragma unroll
        for (int rh = 0; rh < 2; rh++) {        // row half
            int r0 = warp * 8 + rh * 4;
            int acc[4][4];
#pragma unroll
            for (int r = 0; r < 4; r++)
#pragma unroll
                for (int c = 0; c < 4; c++) acc[r][c] = 0;

#pragma unroll 1
            for (int q = 0; q < 7; q++) {
                uint4 a0 = *(const uint4*)&sAct[(r0 + 0) * L0_WPAD + (q << 2)];
                uint4 a1 = *(const uint4*)&sAct[(r0 + 1) * L0_WPAD + (q << 2)];
                uint4 a2 = *(const uint4*)&sAct[(r0 + 2) * L0_WPAD + (q << 2)];
                uint4 a3 = *(const uint4*)&sAct[(r0 + 3) * L0_WPAD + (q << 2)];
#pragma unroll
                for (int c4 = 0; c4 < 4; c4++) {
                    int col = (ch << 7) + (c4 << 5) + lane;
                    uint4 wv = *(const uint4*)&sW[col * L0_WPAD + (q << 2)];
                    acc[0][c4] += popc4(a0, wv);
                    acc[1][c4] += popc4(a1, wv);
                    acc[2][c4] += popc4(a2, wv);
                    acc[3][c4] += popc4(a3, wv);
                }
            }
#pragma unroll
            for (int c4 = 0; c4 < 4; c4++) {
                int col = (ch << 7) + (c4 << 5) + lane;
#pragma unroll
                for (int r = 0; r < 4; r++) {
                    int h = L0_IN - 2 * acc[r][c4];
                    g_H[(rbase + r0 + r) * 256 + col] = (short)h;
                    ls1[c4] += h;
                    ls2[c4] += h * h;
                }
            }
        }
#pragma unroll
        for (int c4 = 0; c4 < 4; c4++) {
            int col = (ch << 7) + (c4 << 5) + lane;
            atomicAdd(&sS1[col], ls1[c4]);
            atomicAdd(&sS2[col], ls2[c4]);
        }
    }
    __syncthreads();
    atomicAdd((unsigned long long*)&g_S1[0][tid], (unsigned long long)(long long)sS1[tid]);
    atomicAdd((unsigned long long*)&g_S2[0][tid], (unsigned long long)(long long)sS2[tid]);
}

// ---------------------------------------------------------------------------
// Middle layers 1..3: block computes prev BN affine, each warp binarizes its
// own 8 rows of g_H into sAct (warp-local sync), then 2x2-split bit GEMM;
// h written back IN-PLACE (block touches only its own rows).
__global__ __launch_bounds__(256, 4) void gemm_mid_kernel(
    int wIdx, int statIdx,
    const float* __restrict__ gPrev, const float* __restrict__ bPrev) {
    __shared__ __align__(16) unsigned int sW[256 * MID_WPAD];   // 12.3 KB
    __shared__ __align__(16) unsigned int sAct[64 * MID_WORDS]; // 2 KB
    __shared__ float2 sN[256];
    __shared__ int sS1[256], sS2[256];
    const unsigned int* __restrict__ Wb = g_WbM[wIdx];
    int tid = threadIdx.x;
    int rbase = blockIdx.x * 64;
    for (int i = tid; i < 256 * MID_WORDS; i += 256) {
        int col = i >> 3, w = i & 7;
        sW[col * MID_WPAD + w] = Wb[i];
    }
    compute_norm(sN, statIdx - 1, gPrev, bPrev);
    sS1[tid] = 0; sS2[tid] = 0;
    __syncthreads();

    int warp = tid >> 5, lane = tid & 31;
    // Per-warp: binarize own 8 rows into sAct (read by this warp only).
#pragma unroll 1
    for (int r = 0; r < 8; r++) {
        int lrow = warp * 8 + r;
        const short* hp = &g_H[(rbase + lrow) * 256];
#pragma unroll
        for (int w = 0; w < 8; w++) {
            int c = (w << 5) + lane;
            float2 nb = sN[c];
            unsigned int m = __ballot_sync(0xffffffffu,
                                           fmaf(nb.x, (float)hp[c], nb.y) >= 0.0f);
            if (lane == w) sAct[lrow * MID_WORDS + w] = m;
        }
    }
    __syncwarp();

#pragma unroll
    for (int ch = 0; ch < 2; ch++) {            // column half
        int ls1[4] = {0, 0, 0, 0}, ls2[4] = {0, 0, 0, 0};
#pragma unroll
        for (int rh = 0; rh < 2; rh++) {        // row half
            int r0 = warp * 8 + rh * 4;
            int acc[4][4];
#pragma unroll
            for (int r = 0; r < 4; r++)
#pragma unroll
                for (int c = 0; c < 4; c++) acc[r][c] = 0;

#pragma unroll
            for (int q = 0; q < 2; q++) {
                uint4 a0 = *(const uint4*)&sAct[(r0 + 0) * MID_WORDS + (q << 2)];
                uint4 a1 = *(const uint4*)&sAct[(r0 + 1) * MID_WORDS + (q << 2)];
                uint4 a2 = *(const uint4*)&sAct[(r0 + 2) * MID_WORDS + (q << 2)];
                uint4 a3 = *(const uint4*)&sAct[(r0 + 3) * MID_WORDS + (q << 2)];
#pragma unroll
                for (int c4 = 0; c4 < 4; c4++) {
                    int col = (ch << 7) + (c4 << 5) + lane;
                    uint4 wv = *(const uint4*)&sW[col * MID_WPAD + (q << 2)];
                    acc[0][c4] += popc4(a0, wv);
                    acc[1][c4] += popc4(a1, wv);
                    acc[2][c4] += popc4(a2, wv);
                    acc[3][c4] += popc4(a3, wv);
                }
            }
#pragma unroll
            for (int c4 = 0; c4 < 4; c4++) {
                int col = (ch << 7) + (c4 << 5) + lane;
#pragma unroll
                for (int r = 0; r < 4; r++) {
                    int h = 256 - 2 * acc[r][c4];
                    g_H[(rbase + r0 + r) * 256 + col] = (short)h;
                    ls1[c4] += h;
                    ls2[c4] += h * h;
                }
            }
        }
#pragma unroll
        for (int c4 = 0; c4 < 4; c4++) {
            int col = (ch << 7) + (c4 << 5) + lane;
            atomicAdd(&sS1[col], ls1[c4]);
            atomicAdd(&sS2[col], ls2[c4]);
        }
    }
    __syncthreads();
    atomicAdd((unsigned long long*)&g_S1[statIdx][tid], (unsigned long long)(long long)sS1[tid]);
    atomicAdd((unsigned long long*)&g_S2[statIdx][tid], (unsigned long long)(long long)sS2[tid]);
}

// ---------------------------------------------------------------------------
// Layer 4: 256 -> 10. Each warp binarizes its own 16 rows of H3 into smem
// (warp-local), lanes 0..9 own the 10 output columns.
__global__ __launch_bounds__(256) void gemm4_kernel(
    const float* __restrict__ g3, const float* __restrict__ b3) {
    __shared__ unsigned int sW[10 * MID_WORDS];
    __shared__ unsigned int sAct[128 * MID_WORDS];  // 4 KB
    __shared__ float2 sN[256];
    int tid = threadIdx.x;
    if (tid < 10 * MID_WORDS) sW[tid] = g_Wb4[tid];
    compute_norm(sN, 3, g3, b3);
    __syncthreads();

    int warp = tid >> 5, lane = tid & 31;
    int rbase = blockIdx.x * 128;
#pragma unroll 1
    for (int r = 0; r < 16; r++) {
        int lrow = warp * 16 + r;
        const short* hp = &g_H[(rbase + lrow) * 256];
#pragma unroll
        for (int w = 0; w < 8; w++) {
            int c = (w << 5) + lane;
            float2 nb = sN[c];
            unsigned int m = __ballot_sync(0xffffffffu,
                                           fmaf(nb.x, (float)hp[c], nb.y) >= 0.0f);
            if (lane == w) sAct[lrow * MID_WORDS + w] = m;
        }
    }
    __syncwarp();

    int ls1 = 0, ls2 = 0;
#pragma unroll 1
    for (int r = 0; r < 16; r++) {
        int lrow = warp * 16 + r;
        if (lane < 10) {
            const unsigned int* ap = &sAct[lrow * MID_WORDS];
            int acc = 0;
#pragma unroll
            for (int w = 0; w < 8; w++)
                acc += __popc(ap[w] ^ sW[lane * MID_WORDS + w]);
            int h = 256 - 2 * acc;
            g_H4[(rbase + lrow) * 10 + lane] = (short)h;
            ls1 += h; ls2 += h * h;
        }
    }
    if (lane < 10) {
        atomicAdd((unsigned long long*)&g_S1[4][lane], (unsigned long long)(long long)ls1);
        atomicAdd((unsigned long long*)&g_S2[4][lane], (unsigned long long)(long long)ls2);
    }
}

// ---------------------------------------------------------------------------
// Final BN (from exact stats) + softmax, thread per row.
__global__ __launch_bounds__(256) void softmax_kernel(
    const float* __restrict__ g4, const float* __restrict__ b4,
    float* __restrict__ out) {
    __shared__ float2 sN[10];
    if (threadIdx.x < 10) {
        int c = threadIdx.x;
        double m = (double)g_S1[4][c] / (double)BATCH;
        double v = (double)g_S2[4][c] / (double)BATCH - m * m;
        double r = 1.0 / sqrt(v + EPSV);
        double A = (double)g4[c] * r;
        sN[c] = make_float2((float)A, (float)((double)b4[c] - A * m));
    }
    __syncthreads();
    int row = blockIdx.x * blockDim.x + threadIdx.x;
    if (row >= BATCH) return;
    float y[10];
    float mx = -1e30f;
#pragma unroll
    for (int i = 0; i < 10; i++) {
        y[i] = fmaf(sN[i].x, (float)g_H4[row * 10 + i], sN[i].y);
        mx = fmaxf(mx, y[i]);
    }
    float s = 0.0f;
#pragma unroll
    for (int i = 0; i < 10; i++) {
        y[i] = expf(y[i] - mx);
        s += y[i];
    }
    float inv = 1.0f / s;
#pragma unroll
    for (int i = 0; i < 10; i++)
        out[row * 10 + i] = y[i] * inv;
}

// ---------------------------------------------------------------------------
extern "C" void kernel_launch(void* const* d_in, const int* in_sizes, int n_in,
                              void* d_out, int out_size) {
    const float* x = (const float*)d_in[0];
    const float *W[5], *G[5], *Bv[5];
    // setup_inputs dict order interleaves (W,g,b); signature order groups them.
    bool interleaved = (n_in >= 16) && (in_sizes[2] == 256) && (in_sizes[3] == 256);
    if (interleaved) {
        int idx = 1;
        for (int k = 0; k < 5; k++) {
            W[k]  = (const float*)d_in[idx + 0];
            G[k]  = (const float*)d_in[idx + 1];
            Bv[k] = (const float*)d_in[idx + 2];
            idx += 3;
        }
    } else {
        for (int k = 0; k < 5; k++) {
            W[k]  = (const float*)d_in[1 + k];
            G[k]  = (const float*)d_in[6 + k];
            Bv[k] = (const float*)d_in[11 + k];
        }
    }

    // Launch order: ncu (-s 5 -c 1) lands on launch #6 = last gemm_mid.
    zero_stats_kernel<<<5, 256>>>();                               // 1
    prep_kernel<<<4226, 256>>>(x, W[0], W[1], W[2], W[3], W[4]);   // 2
    gemm0_kernel<<<BATCH / 64, 256>>>();                           // 3
    gemm_mid_kernel<<<BATCH / 64, 256>>>(0, 1, G[0], Bv[0]);       // 4
    gemm_mid_kernel<<<BATCH / 64, 256>>>(1, 2, G[1], Bv[1]);       // 5
    gemm_mid_kernel<<<BATCH / 64, 256>>>(2, 3, G[2], Bv[2]);       // 6 <- profiled
    gemm4_kernel<<<BATCH / 128, 256>>>(G[3], Bv[3]);               // 7
    softmax_kernel<<<BATCH / 256, 256>>>(G[4], Bv[4], (float*)d_out); // 8
    (void)out_size;
}

// round 17
// speedup vs baseline: 1.2762x; 1.2693x over previous
#include <cuda_runtime.h>

// ---------------------------------------------------------------------------
// Binarized 5-layer MLP, B=32768, fully-fused persistent kernel.
//   L0: 784->256, L1-3: 256->256, L4: 256->10; each layer:
//   binarize(a) @ binarize(W).T  -> training-mode BatchNorm (batch stats)
//   final softmax.
//
// Grid = 128 blocks (1 CTA/SM guaranteed resident on 148 SMs) x 256 threads.
// Block owns 256 rows for the entire network. Software grid barriers
// (atomic counters, zeroed each launch) separate per-layer stat reduction
// from the BN-affine + binarize of the next layer. Exact integer stats
// (S1,S2 i64 atomics), BN affine in double -> bit-exact vs reference.
//
// H is stored in a thread-contiguous permuted layout:
//   g_Hp[row*256 + lane*8 + k] holds h(col = 32k+lane)
// so epilogue = 1 STG.128/row/thread, binarize = 1 LDG.128/row/thread +
// 8 ballots. All GEMM inner loops are smem LDS.128 (conflict-free padded
// strides) + XOR/POPC/IADD only.
// ---------------------------------------------------------------------------

#define BATCH 32768
#define GRIDB 128      // persistent blocks (<= 148 SMs, 1 CTA/SM resident)
#define RPB 256        // rows per block
#define RPW 32         // rows per warp
#define L0_IN 784
#define L0_WORDS 25    // ceil(784/32)
#define L0_WPAD 28     // 28*{0..7} mod 32 distinct 4-groups -> LDS.128 conflict-free
#define MID_WORDS 8
#define MID_WPAD 12    // 12*{0..7} mod 32 distinct 4-groups -> LDS.128 conflict-free
#define EPSV 1e-5

// Scratch (no allocations allowed -> __device__ globals)
__device__ unsigned int g_Xb[BATCH * L0_WPAD];     // packed input bits, stride 28 (zero-padded)
__device__ unsigned int g_Wb0[256 * L0_WPAD];      // packed W0, stride 28 (zero-padded)
__device__ unsigned int g_WbM[3][256 * MID_WORDS]; // packed W1..W3
__device__ unsigned int g_Wb4[10 * MID_WORDS];     // packed W4
__device__ short        g_Hp[BATCH * 256];         // permuted pre-BN activations
__device__ long long    g_S1[5][256];              // per-column sum(h)
__device__ long long    g_S2[5][256];              // per-column sum(h^2)
__device__ int          g_bar[8];                  // grid-barrier counters

// ---------------------------------------------------------------------------
__global__ void zero_kernel() {
    int i = blockIdx.x * 256 + threadIdx.x;
    if (i < 5 * 256) {
        g_S1[i >> 8][i & 255] = 0;
        g_S2[i >> 8][i & 255] = 0;
    }
    if (i < 8) g_bar[i] = 0;
}

// ---------------------------------------------------------------------------
// One warp packs one row with zero padding to `stride` words.
__device__ __forceinline__ void pack_rows(const float* __restrict__ src,
                                          unsigned int* __restrict__ dst,
                                          int row, int rows, int in_dim,
                                          int words, int stride, float sub) {
    if (row >= rows) return;
    int lane = threadIdx.x & 31;
    long base = (long)row * in_dim;
    for (int w = 0; w < stride; w++) {
        int c = (w << 5) + lane;
        bool p = (w < words) && (c < in_dim) && ((src[base + c] - sub) >= 0.0f);
        unsigned int m = __ballot_sync(0xffffffffu, p);
        if (lane == 0) dst[row * stride + w] = m;
    }
}

__global__ __launch_bounds__(256) void prep_kernel(
    const float* __restrict__ x,  const float* __restrict__ W0,
    const float* __restrict__ W1, const float* __restrict__ W2,
    const float* __restrict__ W3, const float* __restrict__ W4) {
    int b = blockIdx.x;
    int warp = threadIdx.x >> 5;
    if (b < 4096) {
        pack_rows(x, g_Xb, b * 8 + warp, BATCH, L0_IN, L0_WORDS, L0_WPAD, 0.5f);
    } else if (b < 4128) {
        pack_rows(W0, g_Wb0, (b - 4096) * 8 + warp, 256, L0_IN, L0_WORDS, L0_WPAD, 0.0f);
    } else if (b < 4160) {
        pack_rows(W1, g_WbM[0], (b - 4128) * 8 + warp, 256, 256, MID_WORDS, MID_WORDS, 0.0f);
    } else if (b < 4192) {
        pack_rows(W2, g_WbM[1], (b - 4160) * 8 + warp, 256, 256, MID_WORDS, MID_WORDS, 0.0f);
    } else if (b < 4224) {
        pack_rows(W3, g_WbM[2], (b - 4192) * 8 + warp, 256, 256, MID_WORDS, MID_WORDS, 0.0f);
    } else {
        pack_rows(W4, g_Wb4, (b - 4224) * 8 + warp, 10, 256, MID_WORDS, MID_WORDS, 0.0f);
    }
}

// ---------------------------------------------------------------------------
__device__ __forceinline__ int popc4(uint4 a, uint4 w) {
    return __popc(a.x ^ w.x) + __popc(a.y ^ w.y)
         + __popc(a.z ^ w.z) + __popc(a.w ^ w.w);
}
__device__ __forceinline__ int lo16(unsigned int v) { return ((int)(v << 16)) >> 16; }
__device__ __forceinline__ int hi16(unsigned int v) { return ((int)v) >> 16; }

// Software grid barrier: safe because GRIDB=128 blocks are all resident
// (1 CTA/SM minimum occupancy on 148 SMs). Counters zeroed per launch.
__device__ __forceinline__ void grid_barrier(int idx) {
    __syncthreads();
    if (threadIdx.x == 0) {
        __threadfence();
        atomicAdd(&g_bar[idx], 1);
        volatile int* p = &g_bar[idx];
        while (*p < GRIDB) { }
        __threadfence();
    }
    __syncthreads();
}

// Per-column BN affine from exact integer stats (L2-fresh loads via __ldcg).
__device__ __forceinline__ void compute_norm(float2* sN, int layer,
                                             const float* __restrict__ g,
                                             const float* __restrict__ b) {
    int c = threadIdx.x;
    double m = (double)__ldcg(&g_S1[layer][c]) / (double)BATCH;
    double v = (double)__ldcg(&g_S2[layer][c]) / (double)BATCH - m * m;
    double r = 1.0 / sqrt(v + EPSV);
    double A = (double)g[c] * r;
    sN[c] = make_float2((float)A, (float)((double)b[c] - A * m));
}

// ---------------------------------------------------------------------------
// Static smem layout (phase-overlapped union), total 45056 B < 48 KB:
//  [0,28672)      L0 weights (256x28)            | mid weights (256x12) [0,12288)
//  [28672,43008)  L0 act chunk (8w x 16r x 28)   | mid act bits (8w x 32r x 8) [12288,20480)
//                                                | sN float2[256] [20480,22528)
//                                                | sW4 [22528,22848) ; sH4 short[2560] [23040,28160)
//  [43008,45056)  sS1/sS2 int[256] each
#define OFF_SW0   0
#define OFF_SA0   28672
#define OFF_SWM   0
#define OFF_SAM   12288
#define OFF_SN    20480
#define OFF_SW4   22528
#define OFF_SH4   23040
#define OFF_SS1   43008
#define OFF_SS2   44032
#define SMEM_SZ   45056

__global__ __launch_bounds__(256, 1) void mlp_kernel(
    const float* __restrict__ G0, const float* __restrict__ B0,
    const float* __restrict__ G1, const float* __restrict__ B1,
    const float* __restrict__ G2, const float* __restrict__ B2,
    const float* __restrict__ G3, const float* __restrict__ B3,
    const float* __restrict__ G4, const float* __restrict__ B4,
    float* __restrict__ out) {
    __shared__ __align__(16) unsigned char SM[SMEM_SZ];
    unsigned int* sW0 = (unsigned int*)(SM + OFF_SW0);
    unsigned int* sA0 = (unsigned int*)(SM + OFF_SA0);
    unsigned int* sWm = (unsigned int*)(SM + OFF_SWM);
    unsigned int* sAm = (unsigned int*)(SM + OFF_SAM);
    float2*       sN  = (float2*)(SM + OFF_SN);
    unsigned int* sW4 = (unsigned int*)(SM + OFF_SW4);
    short*        sH4 = (short*)(SM + OFF_SH4);
    int*          sS1 = (int*)(SM + OFF_SS1);
    int*          sS2 = (int*)(SM + OFF_SS2);

    int tid = threadIdx.x, warp = tid >> 5, lane = tid & 31;
    int rbase = blockIdx.x * RPB;
    int wrow = rbase + warp * RPW;

    // =================== Layer 0 (784 -> 256) ===================
    for (int i = tid; i < 256 * L0_WPAD; i += 256) sW0[i] = g_Wb0[i];
    sS1[tid] = 0; sS2[tid] = 0;
    __syncthreads();

    {
        int ls1[8], ls2[8];
#pragma unroll
        for (int k = 0; k < 8; k++) { ls1[k] = 0; ls2[k] = 0; }

#pragma unroll 1
        for (int chunk = 0; chunk < 2; chunk++) {
            // per-warp: load 16 rows of packed x into smem (7 uint4 per row)
            uint4* dstA = (uint4*)&sA0[warp * 16 * L0_WPAD];
            const uint4* srcA = (const uint4*)&g_Xb[(wrow + chunk * 16) * L0_WPAD];
            for (int i = lane; i < 16 * 7; i += 32) dstA[i] = srcA[i];
            __syncwarp();

#pragma unroll 1
            for (int p2 = 0; p2 < 2; p2++) {
                int r0 = p2 * 8;   // row within chunk
                int acc[8][8];
#pragma unroll
                for (int r = 0; r < 8; r++)
#pragma unroll
                    for (int k = 0; k < 8; k++) acc[r][k] = 0;

#pragma unroll 1
                for (int q = 0; q < 7; q++) {
                    uint4 a[8];
#pragma unroll
                    for (int r = 0; r < 8; r++)
                        a[r] = *(const uint4*)&sA0[(warp * 16 + r0 + r) * L0_WPAD + (q << 2)];
#pragma unroll
                    for (int k = 0; k < 8; k++) {
                        uint4 wv = *(const uint4*)&sW0[((k << 5) + lane) * L0_WPAD + (q << 2)];
#pragma unroll
                        for (int r = 0; r < 8; r++) acc[r][k] += popc4(a[r], wv);
                    }
                }
                int grow0 = wrow + chunk * 16 + r0;
#pragma unroll
                for (int r = 0; r < 8; r++) {
                    unsigned int pk[4];
#pragma unroll
                    for (int k2 = 0; k2 < 4; k2++) {
                        int h0 = L0_IN - 2 * acc[r][k2 * 2];
                        int h1 = L0_IN - 2 * acc[r][k2 * 2 + 1];
                        ls1[k2 * 2] += h0;     ls2[k2 * 2] += h0 * h0;
                        ls1[k2 * 2 + 1] += h1; ls2[k2 * 2 + 1] += h1 * h1;
                        pk[k2] = (unsigned int)(h0 & 0xFFFF) | ((unsigned int)h1 << 16);
                    }
                    *(uint4*)&g_Hp[(grow0 + r) * 256 + lane * 8] =
                        make_uint4(pk[0], pk[1], pk[2], pk[3]);
                }
            }
        }
#pragma unroll
        for (int k = 0; k < 8; k++) {
            atomicAdd(&sS1[(k << 5) + lane], ls1[k]);
            atomicAdd(&sS2[(k << 5) + lane], ls2[k]);
        }
        __syncthreads();
        atomicAdd((unsigned long long*)&g_S1[0][tid], (unsigned long long)(long long)sS1[tid]);
        atomicAdd((unsigned long long*)&g_S2[0][tid], (unsigned long long)(long long)sS2[tid]);
    }
    grid_barrier(0);

    // =================== Layers 1..3 (256 -> 256) ===================
    const float* Gs[4] = {G0, G1, G2, G3};
    const float* Bs[4] = {B0, B1, B2, B3};
#pragma unroll 1
    for (int L = 1; L <= 3; L++) {
        const unsigned int* __restrict__ Wb = g_WbM[L - 1];
        for (int i = tid; i < 256 * MID_WORDS; i += 256) {
            int col = i >> 3, w = i & 7;
            sWm[col * MID_WPAD + w] = Wb[i];
        }
        compute_norm(sN, L - 1, Gs[L - 1], Bs[L - 1]);
        sS1[tid] = 0; sS2[tid] = 0;
        __syncthreads();

        // binarize own 32 rows from g_Hp (LDG.128 + 8 ballots per row)
        float nx[8], ny[8];
#pragma unroll
        for (int k = 0; k < 8; k++) {
            float2 t = sN[(k << 5) + lane];
            nx[k] = t.x; ny[k] = t.y;
        }
#pragma unroll 1
        for (int r = 0; r < RPW; r++) {
            uint4 v = *(const uint4*)&g_Hp[(wrow + r) * 256 + lane * 8];
            unsigned int wd[4] = {v.x, v.y, v.z, v.w};
#pragma unroll
            for (int k = 0; k < 8; k++) {
                int hk = (k & 1) ? hi16(wd[k >> 1]) : lo16(wd[k >> 1]);
                bool pred = fmaf(nx[k], (float)hk, ny[k]) >= 0.0f;
                unsigned int bal = __ballot_sync(0xffffffffu, pred);
                if (lane == k) sAm[(warp * RPW + r) * MID_WORDS + k] = bal;
            }
        }
        __syncwarp();

        int ls1[8], ls2[8];
#pragma unroll
        for (int k = 0; k < 8; k++) { ls1[k] = 0; ls2[k] = 0; }

#pragma unroll 1
        for (int p = 0; p < 4; p++) {
            int r0 = p * 8;
            int acc[8][8];
#pragma unroll
            for (int r = 0; r < 8; r++)
#pragma unroll
                for (int k = 0; k < 8; k++) acc[r][k] = 0;

#pragma unroll
            for (int q = 0; q < 2; q++) {
                uint4 a[8];
#pragma unroll
                for (int r = 0; r < 8; r++)
                    a[r] = *(const uint4*)&sAm[(warp * RPW + r0 + r) * MID_WORDS + (q << 2)];
#pragma unroll
                for (int k = 0; k < 8; k++) {
                    uint4 wv = *(const uint4*)&sWm[((k << 5) + lane) * MID_WPAD + (q << 2)];
#pragma unroll
                    for (int r = 0; r < 8; r++) acc[r][k] += popc4(a[r], wv);
                }
            }
            int grow0 = wrow + r0;
#pragma unroll
            for (int r = 0; r < 8; r++) {
                unsigned int pk[4];
#pragma unroll
                for (int k2 = 0; k2 < 4; k2++) {
                    int h0 = 256 - 2 * acc[r][k2 * 2];
                    int h1 = 256 - 2 * acc[r][k2 * 2 + 1];
                    ls1[k2 * 2] += h0;     ls2[k2 * 2] += h0 * h0;
                    ls1[k2 * 2 + 1] += h1; ls2[k2 * 2 + 1] += h1 * h1;
                    pk[k2] = (unsigned int)(h0 & 0xFFFF) | ((unsigned int)h1 << 16);
                }
                *(uint4*)&g_Hp[(grow0 + r) * 256 + lane * 8] =
                    make_uint4(pk[0], pk[1], pk[2], pk[3]);
            }
        }
#pragma unroll
        for (int k = 0; k < 8; k++) {
            atomicAdd(&sS1[(k << 5) + lane], ls1[k]);
            atomicAdd(&sS2[(k << 5) + lane], ls2[k]);
        }
        __syncthreads();
        atomicAdd((unsigned long long*)&g_S1[L][tid], (unsigned long long)(long long)sS1[tid]);
        atomicAdd((unsigned long long*)&g_S2[L][tid], (unsigned long long)(long long)sS2[tid]);
        grid_barrier(L);
    }

    // =================== Layer 4 (256 -> 10) ===================
    for (int i = tid; i < 10 * MID_WORDS; i += 256) sW4[i] = g_Wb4[i];
    compute_norm(sN, 3, G3, B3);
    __syncthreads();

    {
        float nx[8], ny[8];
#pragma unroll
        for (int k = 0; k < 8; k++) {
            float2 t = sN[(k << 5) + lane];
            nx[k] = t.x; ny[k] = t.y;
        }
#pragma unroll 1
        for (int r = 0; r < RPW; r++) {
            uint4 v = *(const uint4*)&g_Hp[(wrow + r) * 256 + lane * 8];
            unsigned int wd[4] = {v.x, v.y, v.z, v.w};
#pragma unroll
            for (int k = 0; k < 8; k++) {
                int hk = (k & 1) ? hi16(wd[k >> 1]) : lo16(wd[k >> 1]);
                bool pred = fmaf(nx[k], (float)hk, ny[k]) >= 0.0f;
                unsigned int bal = __ballot_sync(0xffffffffu, pred);
                if (lane == k) sAm[(warp * RPW + r) * MID_WORDS + k] = bal;
            }
        }
        __syncwarp();

        int l41 = 0, l42 = 0;
#pragma unroll 1
        for (int r = 0; r < RPW; r++) {
            if (lane < 10) {
                const unsigned int* ap = &sAm[(warp * RPW + r) * MID_WORDS];
                int acc = 0;
#pragma unroll
                for (int w = 0; w < 8; w++)
                    acc += __popc(ap[w] ^ sW4[lane * MID_WORDS + w]);
                int h = 256 - 2 * acc;
                sH4[(warp * RPW + r) * 10 + lane] = (short)h;
                l41 += h; l42 += h * h;
            }
        }
        if (lane < 10) {
            atomicAdd((unsigned long long*)&g_S1[4][lane], (unsigned long long)(long long)l41);
            atomicAdd((unsigned long long*)&g_S2[4][lane], (unsigned long long)(long long)l42);
        }
    }
    grid_barrier(4);

    // =================== BN + softmax ===================
    if (tid < 10) {
        int c = tid;
        double m = (double)__ldcg(&g_S1[4][c]) / (double)BATCH;
        double v = (double)__ldcg(&g_S2[4][c]) / (double)BATCH - m * m;
        double r = 1.0 / sqrt(v + EPSV);
        double A = (double)G4[c] * r;
        sN[c] = make_float2((float)A, (float)((double)B4[c] - A * m));
    }
    __syncthreads();
    {
        float y[10], mx = -1e30f;
#pragma unroll
        for (int i = 0; i < 10; i++) {
            y[i] = fmaf(sN[i].x, (float)sH4[tid * 10 + i], sN[i].y);
            mx = fmaxf(mx, y[i]);
        }
        float s = 0.0f;
#pragma unroll
        for (int i = 0; i < 10; i++) { y[i] = expf(y[i] - mx); s += y[i]; }
        float inv = 1.0f / s;
        long obase = (long)(rbase + tid) * 10;
#pragma unroll
        for (int i = 0; i < 10; i++) out[obase + i] = y[i] * inv;
    }
}

// ---------------------------------------------------------------------------
extern "C" void kernel_launch(void* const* d_in, const int* in_sizes, int n_in,
                              void* d_out, int out_size) {
    const float* x = (const float*)d_in[0];
    const float *W[5], *G[5], *Bv[5];
    // setup_inputs dict order interleaves (W,g,b); signature order groups them.
    bool interleaved = (n_in >= 16) && (in_sizes[2] == 256) && (in_sizes[3] == 256);
    if (interleaved) {
        int idx = 1;
        for (int k = 0; k < 5; k++) {
            W[k]  = (const float*)d_in[idx + 0];
            G[k]  = (const float*)d_in[idx + 1];
            Bv[k] = (const float*)d_in[idx + 2];
            idx += 3;
        }
    } else {
        for (int k = 0; k < 5; k++) {
            W[k]  = (const float*)d_in[1 + k];
            G[k]  = (const float*)d_in[6 + k];
            Bv[k] = (const float*)d_in[11 + k];
        }
    }

    zero_kernel<<<5, 256>>>();                                     // 1
    prep_kernel<<<4226, 256>>>(x, W[0], W[1], W[2], W[3], W[4]);   // 2
    mlp_kernel<<<GRIDB, 256>>>(G[0], Bv[0], G[1], Bv[1], G[2], Bv[2],
                               G[3], Bv[3], G[4], Bv[4],
                               (float*)d_out);                     // 3 <- profiled (#6 = replay 2)
    (void)out_size;
}